// round 5
// baseline (speedup 1.0000x reference)
#include <cuda_runtime.h>
#include <cstdint>

// LBFGS two-loop recursion, cluster-2 D-split version.
// grid = 128 CTAs = 64 batches x 2-CTA clusters; each CTA owns half of D
// (4096 floats). s/y half-rows stream through a 6-stage 32KB SMEM ring via
// cp.async.bulk + mbarrier. Per-step dot: local block reduce (16 warps) then
// a 12-byte DSMEM partial exchange with the peer CTA (st.shared::cluster +
// remote mbarrier arrive.release.cluster) -- no cluster.sync in the loop.

#define MM 32
#define BB 64
#define DD 8192
#define HD (DD / 2)             // 4096 floats per CTA
#define NT 512
#define STAGES 6
#define HROW_BYTES (HD * 4)     // 16 KB
#define STAGE_BYTES (2 * HROW_BYTES)  // 32 KB (s half + y half)
#define SMEM_SMALL 1024
#define SMEM_TOTAL (SMEM_SMALL + STAGES * STAGE_BYTES)  // 197632

// small-region byte offsets
#define OFF_TMAMBAR 0      // 6 x 8B
#define OFF_XMBAR   64     // 8B
#define OFF_RED     128    // 3 x 16 floats = 192B
#define OFF_FIN     320    // broadcast coefficient (1 float)
#define OFF_GS      336    // gscale (1 float)
#define OFF_XBUF    384    // 2 parity x 16B
#define OFF_RARR    448    // 32 floats
#define OFF_AARR    576    // 32 floats

__device__ __forceinline__ uint32_t smem_u32(const void* p) {
    return (uint32_t)__cvta_generic_to_shared(p);
}

__device__ __forceinline__ void mbar_init(uint32_t mbar, uint32_t count) {
    asm volatile("mbarrier.init.shared::cta.b64 [%0], %1;" :: "r"(mbar), "r"(count));
}

__device__ __forceinline__ void mbar_expect_tx(uint32_t mbar, uint32_t bytes) {
    asm volatile("mbarrier.arrive.expect_tx.shared::cta.b64 _, [%0], %1;"
                 :: "r"(mbar), "r"(bytes) : "memory");
}

__device__ __forceinline__ void bulk_g2s(uint32_t dst, const void* src,
                                         uint32_t bytes, uint32_t mbar) {
    asm volatile(
        "cp.async.bulk.shared::cluster.global.mbarrier::complete_tx::bytes "
        "[%0], [%1], %2, [%3];"
        :: "r"(dst), "l"(src), "r"(bytes), "r"(mbar) : "memory");
}

__device__ __forceinline__ void mbar_wait(uint32_t mbar, uint32_t parity) {
    uint32_t done;
    asm volatile(
        "{\n\t.reg .pred p;\n\t"
        "mbarrier.try_wait.parity.acquire.cta.shared::cta.b64 p, [%1], %2;\n\t"
        "selp.b32 %0, 1, 0, p;\n\t}"
        : "=r"(done) : "r"(mbar), "r"(parity) : "memory");
    if (!done) {
        asm volatile(
            "{\n\t.reg .pred P1;\n\t"
            "WL_%=:\n\t"
            "mbarrier.try_wait.parity.acquire.cta.shared::cta.b64 P1, [%0], %1, 0x989680;\n\t"
            "@P1 bra.uni WD_%=;\n\t"
            "bra.uni WL_%=;\n\t"
            "WD_%=:\n\t}"
            :: "r"(mbar), "r"(parity) : "memory");
    }
}

// cluster-scope acquire wait (for the DSMEM exchange barrier)
__device__ __forceinline__ void mbar_wait_cluster(uint32_t mbar, uint32_t parity) {
    uint32_t done;
    asm volatile(
        "{\n\t.reg .pred p;\n\t"
        "mbarrier.try_wait.parity.acquire.cluster.shared::cta.b64 p, [%1], %2;\n\t"
        "selp.b32 %0, 1, 0, p;\n\t}"
        : "=r"(done) : "r"(mbar), "r"(parity) : "memory");
    if (!done) {
        asm volatile(
            "{\n\t.reg .pred P1;\n\t"
            "XL_%=:\n\t"
            "mbarrier.try_wait.parity.acquire.cluster.shared::cta.b64 P1, [%0], %1, 0x989680;\n\t"
            "@P1 bra.uni XD_%=;\n\t"
            "bra.uni XL_%=;\n\t"
            "XD_%=:\n\t}"
            :: "r"(mbar), "r"(parity) : "memory");
    }
}

__device__ __forceinline__ uint32_t mapa_u32(uint32_t local_addr, uint32_t rank) {
    uint32_t r;
    asm("mapa.shared::cluster.u32 %0, %1, %2;" : "=r"(r) : "r"(local_addr), "r"(rank));
    return r;
}

__device__ __forceinline__ float dot4(float4 a, float4 b) {
    return a.x * b.x + a.y * b.y + a.z * b.z + a.w * b.w;
}

__device__ __forceinline__ int seq_row(int t) {  // palindromic order
    return (t < MM) ? (MM - 1 - t) : (t - MM);
}

__global__ __launch_bounds__(NT, 1) __cluster_dims__(2, 1, 1)
void lbfgs_cluster_kernel(const float* __restrict__ S,
                          const float* __restrict__ Y,
                          const float* __restrict__ FRC,
                          float* __restrict__ OUT) {
    extern __shared__ __align__(1024) char smem[];

    uint32_t rank;
    asm("mov.u32 %0, %%cluster_ctarank;" : "=r"(rank));
    const int b    = blockIdx.x >> 1;
    const int half = (int)rank;
    const int tid  = threadIdx.x;
    const int lane = tid & 31;
    const int wid  = tid >> 5;

    float* red    = (float*)(smem + OFF_RED);
    float* fin    = (float*)(smem + OFF_FIN);
    float* gsv    = (float*)(smem + OFF_GS);
    float* xbuf   = (float*)(smem + OFF_XBUF);
    float* r_arr  = (float*)(smem + OFF_RARR);
    float* a_arr  = (float*)(smem + OFF_AARR);

    const uint32_t mbar0      = smem_u32(smem + OFF_TMAMBAR);
    const uint32_t xmbar      = smem_u32(smem + OFF_XMBAR);
    const uint32_t xbuf_u32   = smem_u32(smem + OFF_XBUF);
    const uint32_t stage0     = smem_u32(smem + SMEM_SMALL);
    const uint32_t peer       = rank ^ 1u;
    const uint32_t xmbar_peer = mapa_u32(xmbar, peer);
    const uint32_t xbuf_peer  = mapa_u32(xbuf_u32, peer);

    if (tid == 0) {
#pragma unroll
        for (int s = 0; s < STAGES; ++s) mbar_init(mbar0 + s * 8, 1);
        mbar_init(xmbar, 1);
    }
    asm volatile("fence.proxy.async.shared::cta;" ::: "memory");
    __syncthreads();
    // all mbarriers (both CTAs) initialized before any remote arrive
    asm volatile("barrier.cluster.arrive.aligned;" ::: "memory");
    asm volatile("barrier.cluster.wait.aligned;" ::: "memory");

    auto issue = [&](int stage, int t) {
        const int row = seq_row(t);
        const size_t off = ((size_t)row * BB + b) * DD + (size_t)half * HD;
        const uint32_t m   = mbar0 + stage * 8;
        const uint32_t dst = stage0 + stage * STAGE_BYTES;
        mbar_expect_tx(m, STAGE_BYTES);
        bulk_g2s(dst,              S + off, HROW_BYTES, m);
        bulk_g2s(dst + HROW_BYTES, Y + off, HROW_BYTES, m);
    };

    if (tid == 0) {
#pragma unroll
        for (int s = 0; s < STAGES; ++s) issue(s, s);
    }

    // q = -frc (half-D, register-resident: 8 floats)
    float4 q0, q1;
    {
        const float4* F4 = (const float4*)(FRC + (size_t)b * DD + (size_t)half * HD);
        float4 a = F4[tid], c = F4[tid + NT];
        q0.x = -a.x; q0.y = -a.y; q0.z = -a.z; q0.w = -a.w;
        q1.x = -c.x; q1.y = -c.y; q1.z = -c.z; q1.w = -c.w;
    }

#pragma unroll 1
    for (int t = 0; t < 2 * MM; ++t) {
        const int stage = t % STAGES;
        const uint32_t tparity = (uint32_t)(t / STAGES) & 1u;
        const uint32_t xparity = (uint32_t)t & 1u;

        if (t == MM) {  // between passes: q *= g (gsv written at t=0, barrier-ordered)
            const float g = gsv[0];
            q0.x *= g; q0.y *= g; q0.z *= g; q0.w *= g;
            q1.x *= g; q1.y *= g; q1.z *= g; q1.w *= g;
        }

        mbar_wait(mbar0 + stage * 8, tparity);

        const float4* sS = (const float4*)(smem + SMEM_SMALL + stage * STAGE_BYTES);
        const float4* sY = (const float4*)(smem + SMEM_SMALL + stage * STAGE_BYTES + HROW_BYTES);
        float4 s0 = sS[tid], s1 = sS[tid + NT];
        float4 y0 = sY[tid], y1 = sY[tid + NT];

        const bool bwd = (t < MM);
        const int  i   = bwd ? (MM - 1 - t) : (t - MM);

        // ---- local partials ----
        float v0, v1, v2;
        if (bwd) {
            v0 = dot4(s0, y0) + dot4(s1, y1);      // s.y
            v1 = dot4(s0, q0) + dot4(s1, q1);      // s.q
            v2 = (t == 0) ? (dot4(y0, y0) + dot4(y1, y1)) : 0.0f;
        } else {
            v0 = dot4(y0, q0) + dot4(y1, q1);      // y.q
            v1 = 0.0f; v2 = 0.0f;
        }

        // warp reduce (only the values in play)
#pragma unroll
        for (int off = 16; off > 0; off >>= 1) {
            v0 += __shfl_xor_sync(0xffffffffu, v0, off);
            if (bwd) v1 += __shfl_xor_sync(0xffffffffu, v1, off);
            if (bwd && t == 0) v2 += __shfl_xor_sync(0xffffffffu, v2, off);
        }
        if (lane == 0) {
            red[wid] = v0;
            if (bwd) red[16 + wid] = v1;
            if (bwd && t == 0) red[32 + wid] = v2;
        }
        __syncthreads();   // stage fully consumed; partials posted

        // warp1 refills the ring while warp0 finishes the reduction
        if (tid == 32 && t + STAGES < 2 * MM) issue(stage, t + STAGES);

        if (wid == 0) {
            const int l16 = lane & 15;
            float x0 = red[l16];
            float x1 = bwd ? red[16 + l16] : 0.0f;
            float x2 = (bwd && t == 0) ? red[32 + l16] : 0.0f;
#pragma unroll
            for (int off = 8; off > 0; off >>= 1) {
                x0 += __shfl_xor_sync(0xffffffffu, x0, off);
                x1 += __shfl_xor_sync(0xffffffffu, x1, off);
                x2 += __shfl_xor_sync(0xffffffffu, x2, off);
            }
            if (lane == 0) {
                // ---- DSMEM exchange with peer CTA (12 bytes) ----
                const uint32_t wdst = xbuf_peer + xparity * 16;
                uint64_t p01;
                asm("mov.b64 %0, {%1, %2};" : "=l"(p01) : "f"(x0), "f"(x1));
                asm volatile("st.shared::cluster.b64 [%0], %1;" :: "r"(wdst), "l"(p01) : "memory");
                asm volatile("st.shared::cluster.f32 [%0], %1;" :: "r"(wdst + 8), "f"(x2) : "memory");
                asm volatile("mbarrier.arrive.release.cluster.shared::cluster.b64 _, [%0];"
                             :: "r"(xmbar_peer) : "memory");
                mbar_wait_cluster(xmbar, xparity);
                const float* rb = xbuf + xparity * 4;
                const float t0 = x0 + rb[0];
                const float t1 = x1 + rb[1];
                const float t2 = x2 + rb[2];

                if (bwd) {
                    const float r = 1.0f / t0;
                    const float a = r * t1;
                    r_arr[i] = r; a_arr[i] = a;
                    fin[0] = a;
                    if (t == 0) gsv[0] = t0 / t2;
                } else {
                    fin[0] = a_arr[i] - r_arr[i] * t0;
                }
            }
        }
        __syncthreads();

        const float cf = fin[0];
        if (bwd) {
            q0.x -= cf * y0.x; q0.y -= cf * y0.y; q0.z -= cf * y0.z; q0.w -= cf * y0.w;
            q1.x -= cf * y1.x; q1.y -= cf * y1.y; q1.z -= cf * y1.z; q1.w -= cf * y1.w;
        } else {
            q0.x += cf * s0.x; q0.y += cf * s0.y; q0.z += cf * s0.z; q0.w += cf * s0.w;
            q1.x += cf * s1.x; q1.y += cf * s1.y; q1.z += cf * s1.z; q1.w += cf * s1.w;
        }
    }

    // out = -q
    float4* O4 = (float4*)(OUT + (size_t)b * DD + (size_t)half * HD);
    float4 o0, o1;
    o0.x = -q0.x; o0.y = -q0.y; o0.z = -q0.z; o0.w = -q0.w;
    o1.x = -q1.x; o1.y = -q1.y; o1.z = -q1.z; o1.w = -q1.w;
    O4[tid]      = o0;
    O4[tid + NT] = o1;

    // don't exit while peer traffic may still target this CTA's smem
    asm volatile("barrier.cluster.arrive.aligned;" ::: "memory");
    asm volatile("barrier.cluster.wait.aligned;" ::: "memory");
}

extern "C" void kernel_launch(void* const* d_in, const int* in_sizes, int n_in,
                              void* d_out, int out_size) {
    const float* S   = (const float*)d_in[0];  // (M, B, D) fp32
    const float* Y   = (const float*)d_in[1];  // (M, B, D) fp32
    const float* FRC = (const float*)d_in[2];  // (B, D)    fp32
    float* OUT = (float*)d_out;                // (B, D)    fp32

    static bool attr_set = false;
    if (!attr_set) {
        cudaFuncSetAttribute(lbfgs_cluster_kernel,
                             cudaFuncAttributeMaxDynamicSharedMemorySize,
                             SMEM_TOTAL);
        attr_set = true;
    }
    lbfgs_cluster_kernel<<<2 * BB, NT, SMEM_TOTAL>>>(S, Y, FRC, OUT);
}